// round 1
// baseline (speedup 1.0000x reference)
#include <cuda_runtime.h>
#include <cstdint>
#include <cstdio>

#define NN      50000
#define EE      800000
#define DINV    256
#define HD      128
#define RRk     8
#define NHEADS  8
#define DHH     16

// ---------------- scratch (static device allocations; no cudaMalloc) -------------
__device__ float g_h1[(size_t)NN * HD];
__device__ float g_h2[(size_t)NN * HD];
__device__ float g_v[(size_t)NN * RRk * HD];     // per-relation mean aggregate (204.8 MB)
__device__ float g_num[(size_t)NN * HD];
__device__ int   g_deg[(size_t)NN * RRk];
__device__ float g_asrc[(size_t)NN * NHEADS];
__device__ float g_atgt[(size_t)NN * NHEADS];
__device__ float g_amax[(size_t)NN * NHEADS];
__device__ float g_denom[(size_t)NN * NHEADS];

// ---------------- packed fp32x2 helpers (Blackwell FFMA2 path) -------------------
typedef unsigned long long u64;

__device__ __forceinline__ u64 pk2(float lo, float hi) {
    u64 r; asm("mov.b64 %0, {%1, %2};" : "=l"(r) : "f"(lo), "f"(hi)); return r;
}
__device__ __forceinline__ float2 up2(u64 v) {
    float2 f; asm("mov.b64 {%0, %1}, %2;" : "=f"(f.x), "=f"(f.y) : "l"(v)); return f;
}
__device__ __forceinline__ u64 ffma2(u64 a, u64 b, u64 c) {
    u64 d; asm("fma.rn.f32x2 %0, %1, %2, %3;" : "=l"(d) : "l"(a), "l"(b), "l"(c)); return d;
}

// vector reduction (sm_90+): 1 instruction instead of 4 scalar REDs
__device__ __forceinline__ void red_add_v4(float* p, float a, float b, float c, float d) {
    asm volatile("red.global.add.v4.f32 [%0], {%1, %2, %3, %4};"
                 :: "l"(p), "f"(a), "f"(b), "f"(c), "f"(d) : "memory");
}

__device__ __forceinline__ void atomicMaxFloat(float* addr, float val) {
    if (val >= 0.f) atomicMax(reinterpret_cast<int*>(addr), __float_as_int(val));
    else            atomicMin(reinterpret_cast<unsigned int*>(addr), __float_as_uint(val));
}

// ---------------- generic 128-wide fp32 GEMM: C = relu?( [A0|A1] @ [B0;B1] + bias )
// A0: [M,K0] row-major, A1: [M,K1] row-major, B0: [K0,128], B1: [K1,128] row-major.
// Block tile 128x128, K-tile 16, 256 threads, 8x8 per thread, packed f32x2 FMA.
__global__ __launch_bounds__(256, 2)
void gemm_f32(const float* __restrict__ A0, int K0,
              const float* __restrict__ A1, int K1,
              const float* __restrict__ B0, const float* __restrict__ B1,
              const float* __restrict__ bias,
              float* __restrict__ C, int M, int do_relu)
{
    __shared__ float As[16][128];
    __shared__ float Bs[16][128];
    const int tid   = threadIdx.x;
    const int m0    = blockIdx.x * 128;
    const int tx    = tid & 15;
    const int ty    = tid >> 4;
    const int a_row = tid >> 2;
    const int a_col = (tid & 3) << 2;
    const int b_row = tid >> 5;
    const int b_col = (tid & 31) << 2;
    const int KT    = K0 + K1;

    u64 acc[8][4];
#pragma unroll
    for (int i = 0; i < 8; i++)
#pragma unroll
        for (int j = 0; j < 4; j++) acc[i][j] = 0ull;

    for (int k0 = 0; k0 < KT; k0 += 16) {
        const float* A; int lda, ac;
        const float* B; int br;
        if (k0 < K0) { A = A0; lda = K0; ac = k0;      B = B0; br = k0;      }
        else         { A = A1; lda = K1; ac = k0 - K0; B = B1; br = k0 - K0; }

#pragma unroll
        for (int r2 = 0; r2 < 2; r2++) {
            int m = m0 + a_row + r2 * 64;
            float4 av = make_float4(0.f, 0.f, 0.f, 0.f);
            if (m < M) av = *reinterpret_cast<const float4*>(&A[(size_t)m * lda + ac + a_col]);
            As[a_col + 0][a_row + r2 * 64] = av.x;
            As[a_col + 1][a_row + r2 * 64] = av.y;
            As[a_col + 2][a_row + r2 * 64] = av.z;
            As[a_col + 3][a_row + r2 * 64] = av.w;
        }
#pragma unroll
        for (int r2 = 0; r2 < 2; r2++) {
            int kk = b_row + r2 * 8;
            *reinterpret_cast<float4*>(&Bs[kk][b_col]) =
                *reinterpret_cast<const float4*>(&B[(size_t)(br + kk) * HD + b_col]);
        }
        __syncthreads();

#pragma unroll
        for (int kk = 0; kk < 16; kk++) {
            float4 alo = *reinterpret_cast<const float4*>(&As[kk][ty * 8]);
            float4 ahi = *reinterpret_cast<const float4*>(&As[kk][ty * 8 + 4]);
            float4 blo = *reinterpret_cast<const float4*>(&Bs[kk][tx * 8]);
            float4 bhi = *reinterpret_cast<const float4*>(&Bs[kk][tx * 8 + 4]);
            u64 b01 = pk2(blo.x, blo.y), b23 = pk2(blo.z, blo.w);
            u64 b45 = pk2(bhi.x, bhi.y), b67 = pk2(bhi.z, bhi.w);
            float aa[8] = {alo.x, alo.y, alo.z, alo.w, ahi.x, ahi.y, ahi.z, ahi.w};
#pragma unroll
            for (int i = 0; i < 8; i++) {
                u64 ad = pk2(aa[i], aa[i]);
                acc[i][0] = ffma2(ad, b01, acc[i][0]);
                acc[i][1] = ffma2(ad, b23, acc[i][1]);
                acc[i][2] = ffma2(ad, b45, acc[i][2]);
                acc[i][3] = ffma2(ad, b67, acc[i][3]);
            }
        }
        __syncthreads();
    }

    float bvals[8];
#pragma unroll
    for (int j = 0; j < 8; j++) bvals[j] = bias ? bias[tx * 8 + j] : 0.f;
#pragma unroll
    for (int i = 0; i < 8; i++) {
        int m = m0 + ty * 8 + i;
        if (m >= M) continue;
        float o[8];
#pragma unroll
        for (int j = 0; j < 4; j++) { float2 f = up2(acc[i][j]); o[2 * j] = f.x; o[2 * j + 1] = f.y; }
#pragma unroll
        for (int j = 0; j < 8; j++) { o[j] += bvals[j]; if (do_relu) o[j] = fmaxf(o[j], 0.f); }
        *reinterpret_cast<float4*>(&C[(size_t)m * HD + tx * 8])     = make_float4(o[0], o[1], o[2], o[3]);
        *reinterpret_cast<float4*>(&C[(size_t)m * HD + tx * 8 + 4]) = make_float4(o[4], o[5], o[6], o[7]);
    }
}

// ---------------- graph kernels ---------------------------------------------------
__global__ void deg_kernel(const int* __restrict__ tgt, const int* __restrict__ et, int E) {
    int i = blockIdx.x * blockDim.x + threadIdx.x;
    if (i < E) atomicAdd(&g_deg[(size_t)tgt[i] * RRk + et[i]], 1);
}

// one warp per edge: v[tgt, etype, :] += h[src, :] / max(deg,1)
__global__ void rgcn_scatter(const float* __restrict__ h, const int* __restrict__ src,
                             const int* __restrict__ tgt, const int* __restrict__ et, int E) {
    int w    = (blockIdx.x * blockDim.x + threadIdx.x) >> 5;
    int lane = threadIdx.x & 31;
    if (w >= E) return;
    int s = src[w], t = tgt[w], r = et[w];
    int d = g_deg[(size_t)t * RRk + r];
    float inv = 1.f / (float)(d > 1 ? d : 1);
    float4 hv = *reinterpret_cast<const float4*>(&h[(size_t)s * HD + lane * 4]);
    red_add_v4(&g_v[(size_t)t * (RRk * HD) + r * HD + lane * 4],
               hv.x * inv, hv.y * inv, hv.z * inv, hv.w * inv);
}

// per-node attention halves: asrc[n,h] = z[n,h,:]·att_l[h], atgt = ·att_r[h]
__global__ void gat_alpha(const float* __restrict__ z, const float* __restrict__ att, int N) {
    int i = blockIdx.x * blockDim.x + threadIdx.x;
    if (i >= N * NHEADS) return;
    int n = i >> 3, h = i & 7;
    const float* zp = &z[(size_t)n * HD + h * DHH];
    float ss = 0.f, st = 0.f;
#pragma unroll
    for (int d = 0; d < DHH; d++) {
        float zv = zp[d];
        ss += zv * att[h * 2 * DHH + d];
        st += zv * att[h * 2 * DHH + DHH + d];
    }
    g_asrc[i] = ss; g_atgt[i] = st;
}

__global__ void init_amax(int n) {
    int i = blockIdx.x * blockDim.x + threadIdx.x;
    if (i < n) g_amax[i] = -1e30f;
}

__global__ void gat_max(const int* __restrict__ src, const int* __restrict__ tgt, int E) {
    int i = blockIdx.x * blockDim.x + threadIdx.x;
    if (i >= E * NHEADS) return;
    int e = i >> 3, h = i & 7;
    int s = src[e], t = tgt[e];
    float a = g_asrc[s * NHEADS + h] + g_atgt[t * NHEADS + h];
    a = (a > 0.f) ? a : 0.2f * a;
    atomicMaxFloat(&g_amax[t * NHEADS + h], a);
}

// one warp per edge: num[tgt,:] += z[src,:]*exp(alpha - amax[tgt]), denom[tgt,h] += exp
__global__ void gat_accum(const float* __restrict__ z, const int* __restrict__ src,
                          const int* __restrict__ tgt, int E) {
    int w    = (blockIdx.x * blockDim.x + threadIdx.x) >> 5;
    int lane = threadIdx.x & 31;
    if (w >= E) return;
    int s = src[w], t = tgt[w];
    int head = lane >> 2;              // 4 consecutive floats stay within one head (DH=16)
    float a = g_asrc[s * NHEADS + head] + g_atgt[t * NHEADS + head];
    a = (a > 0.f) ? a : 0.2f * a;
    float ex = __expf(a - g_amax[t * NHEADS + head]);
    float4 zv = *reinterpret_cast<const float4*>(&z[(size_t)s * HD + lane * 4]);
    red_add_v4(&g_num[(size_t)t * HD + lane * 4],
               zv.x * ex, zv.y * ex, zv.z * ex, zv.w * ex);
    if ((lane & 3) == 0) atomicAdd(&g_denom[t * NHEADS + head], ex);
}

// one warp per node: g = num/denom + bg ; logits = g @ Wf + bf ; log_softmax
__global__ void final_kernel(const float* __restrict__ bg, const float* __restrict__ Wf,
                             const float* __restrict__ bf, float* __restrict__ out, int N) {
    int w    = (blockIdx.x * blockDim.x + threadIdx.x) >> 5;
    int lane = threadIdx.x & 31;
    if (w >= N) return;
    int f0 = lane * 4;
    int head = lane >> 2;
    float4 nm = *reinterpret_cast<const float4*>(&g_num[(size_t)w * HD + f0]);
    float den = fmaxf(g_denom[w * NHEADS + head], 1e-16f);
    float gv[4] = { nm.x / den + bg[f0], nm.y / den + bg[f0 + 1],
                    nm.z / den + bg[f0 + 2], nm.w / den + bg[f0 + 3] };
    float s0 = 0.f, s1 = 0.f, s2 = 0.f;
#pragma unroll
    for (int i = 0; i < 4; i++) {
        const float* wr = &Wf[(f0 + i) * 3];
        s0 += gv[i] * wr[0]; s1 += gv[i] * wr[1]; s2 += gv[i] * wr[2];
    }
#pragma unroll
    for (int o = 16; o > 0; o >>= 1) {
        s0 += __shfl_xor_sync(0xffffffffu, s0, o);
        s1 += __shfl_xor_sync(0xffffffffu, s1, o);
        s2 += __shfl_xor_sync(0xffffffffu, s2, o);
    }
    if (lane == 0) {
        float l0 = s0 + bf[0], l1 = s1 + bf[1], l2 = s2 + bf[2];
        float m = fmaxf(l0, fmaxf(l1, l2));
        float lse = m + logf(expf(l0 - m) + expf(l1 - m) + expf(l2 - m));
        out[w * 3 + 0] = l0 - lse;
        out[w * 3 + 1] = l1 - lse;
        out[w * 3 + 2] = l2 - lse;
    }
}

// ---------------- host ------------------------------------------------------------
extern "C" void kernel_launch(void* const* d_in, const int* in_sizes, int n_in,
                              void* d_out, int out_size)
{
    const float* x   = (const float*)d_in[0];
    const int*   ei  = (const int*)d_in[1];
    const int*   et  = (const int*)d_in[2];
    const float* Wp  = (const float*)d_in[3];
    const float* bp  = (const float*)d_in[4];
    const float* W1  = (const float*)d_in[5];
    const float* r1  = (const float*)d_in[6];
    const float* b1  = (const float*)d_in[7];
    const float* W2  = (const float*)d_in[8];
    const float* r2  = (const float*)d_in[9];
    const float* b2  = (const float*)d_in[10];
    const float* Wg  = (const float*)d_in[11];
    const float* att = (const float*)d_in[12];
    const float* bg  = (const float*)d_in[13];
    const float* Wf  = (const float*)d_in[14];
    const float* bf  = (const float*)d_in[15];
    float* out = (float*)d_out;

    const int N = in_sizes[0] / DINV;
    const int E = in_sizes[2];
    const int* src = ei;
    const int* tg  = ei + E;

    void *p_h1, *p_h2, *p_v, *p_num, *p_deg, *p_denom;
    cudaGetSymbolAddress(&p_h1, g_h1);
    cudaGetSymbolAddress(&p_h2, g_h2);
    cudaGetSymbolAddress(&p_v, g_v);
    cudaGetSymbolAddress(&p_num, g_num);
    cudaGetSymbolAddress(&p_deg, g_deg);
    cudaGetSymbolAddress(&p_denom, g_denom);
    float* h1 = (float*)p_h1;
    float* h2 = (float*)p_h2;
    float* v  = (float*)p_v;

    const int gemm_grid = (N + 127) / 128;

    // h = x @ Wp + bp
    gemm_f32<<<gemm_grid, 256>>>(x, DINV, nullptr, 0, Wp, nullptr, bp, h1, N, 0);

    // in-degrees per relation (same for both RGCN layers)
    cudaMemsetAsync(p_deg, 0, (size_t)N * RRk * sizeof(int), 0);
    deg_kernel<<<(E + 255) / 256, 256>>>(tg, et, E);

    // RGCN layer 1: aggregate then GEMM
    cudaMemsetAsync(p_v, 0, (size_t)N * RRk * HD * sizeof(float), 0);
    rgcn_scatter<<<(E + 7) / 8, 256>>>(h1, src, tg, et, E);
    gemm_f32<<<gemm_grid, 256>>>(h1, HD, v, RRk * HD, r1, W1, b1, h2, N, 1);

    // RGCN layer 2
    cudaMemsetAsync(p_v, 0, (size_t)N * RRk * HD * sizeof(float), 0);
    rgcn_scatter<<<(E + 7) / 8, 256>>>(h2, src, tg, et, E);
    gemm_f32<<<gemm_grid, 256>>>(h2, HD, v, RRk * HD, r2, W2, b2, h1, N, 1);

    // GAT: z = h @ Wg  (z stored in h2)
    gemm_f32<<<gemm_grid, 256>>>(h1, HD, nullptr, 0, Wg, nullptr, nullptr, h2, N, 0);
    gat_alpha<<<(N * NHEADS + 255) / 256, 256>>>(h2, att, N);
    init_amax<<<(N * NHEADS + 255) / 256, 256>>>(N * NHEADS);
    cudaMemsetAsync(p_denom, 0, (size_t)N * NHEADS * sizeof(float), 0);
    cudaMemsetAsync(p_num, 0, (size_t)N * HD * sizeof(float), 0);
    gat_max<<<(E * NHEADS + 255) / 256, 256>>>(src, tg, E);
    gat_accum<<<(E + 7) / 8, 256>>>(h2, src, tg, E);

    // logits + log_softmax
    final_kernel<<<(N + 7) / 8, 256>>>(bg, Wf, bf, out, N);
}